// round 4
// baseline (speedup 1.0000x reference)
#include <cuda_runtime.h>
#include <math.h>

#define THREADS 256
#define JT      256
#define MAXBLK  8192

typedef unsigned long long ull;

// Per-block partial sums: [0,tpj) = Sxz, [tpj,2tpj) = Sxx(upper), [2tpj,3tpj) = Szz(upper)
__device__ float    g_part[MAXBLK];
__device__ unsigned g_ticket = 0;

__device__ __forceinline__ float ex2f(float v) {
    float y;
    asm("ex2.approx.ftz.f32 %0, %1;" : "=f"(y) : "f"(v));
    return y;
}

// Single fused kernel: inline prep (scale + pack), passthrough copy, pair sums,
// and final scalar via last-block threadfence reduction.
// Job 0: xz (full grid), job 1: xx (strict upper), job 2: zz (strict upper).
__global__ void __launch_bounds__(THREADS) pair_kernel(
    const float* __restrict__ x, const float* __restrict__ z,
    const float* __restrict__ ks, const float* __restrict__ theta,
    float* __restrict__ out, int n)
{
    const int iTiles = n / THREADS;
    const int jSlabs = n / JT;
    const int tpj = iTiles * jSlabs;

    const int b = blockIdx.x;
    const int job = b / tpj;
    const int rem = b - job * tpj;
    const int it = rem % iTiles;
    const int js = rem / iTiles;
    const int tid = threadIdx.x;

    // ---- Passthrough copy: out[0..3n) = x, out[3n..6n) = z, sliced by block ----
    {
        const int total = 6 * n;
        const int per = (total + gridDim.x - 1) / gridDim.x;
        const int start = b * per;
        const int stop = min(start + per, total);
        for (int idx = start + tid; idx < stop; idx += THREADS)
            out[idx] = (idx < 3 * n) ? x[idx] : z[idx - 3 * n];
    }

    const bool sym = (job >= 1);
    const int i0 = it * THREADS;
    const int j0 = js * JT;
    const bool empty = sym && (js < it);   // entirely below diagonal

    if (!empty) {
        const float* A = (job == 2) ? z : x;
        const float* B = (job == 1) ? x : z;

        const float sc = sqrtf(1.4426950408889634f / ks[0]);   // sqrt(log2e / ks)

        // B slab, packed-pairs layout for f32x2 math:
        //   sB[2*g]   = (bx0, bx1, by0, by1)
        //   sB[2*g+1] = (bz0, bz1, w0,  w1)    w = -|b|^2 (scaled)
        __shared__ float4 sB[JT];
        for (int g = tid; g < JT / 2; g += THREADS) {
            int ja = j0 + 2 * g, jb = ja + 1;
            float b0x = B[3 * ja]     * sc, b0y = B[3 * ja + 1] * sc, b0z = B[3 * ja + 2] * sc;
            float b1x = B[3 * jb]     * sc, b1y = B[3 * jb + 1] * sc, b1z = B[3 * jb + 2] * sc;
            float w0 = -(b0x * b0x + b0y * b0y + b0z * b0z);
            float w1 = -(b1x * b1x + b1y * b1y + b1z * b1z);
            sB[2 * g]     = make_float4(b0x, b1x, b0y, b1y);
            sB[2 * g + 1] = make_float4(b0z, b1z, w0, w1);
        }

        // A point for this thread: doubled scaled coords; aw = -|a|^2.
        const int i = i0 + tid;
        const float ax = A[3 * i]     * sc * 2.f;
        const float ay = A[3 * i + 1] * sc * 2.f;
        const float az = A[3 * i + 2] * sc * 2.f;
        const float aw = -0.25f * (ax * ax + ay * ay + az * az);
        __syncthreads();

        float acc0 = 0.f, acc1 = 0.f;

        if (!(sym && js == it)) {
            // Full tile: predicate-free packed loop, 2 j's per iteration.
            ull ax2, ay2, az2;
            asm("mov.b64 %0, {%1,%1};" : "=l"(ax2) : "f"(ax));
            asm("mov.b64 %0, {%1,%1};" : "=l"(ay2) : "f"(ay));
            asm("mov.b64 %0, {%1,%1};" : "=l"(az2) : "f"(az));
            unsigned sb = (unsigned)__cvta_generic_to_shared(sB);
#pragma unroll 8
            for (int k2 = 0; k2 < JT / 2; k2++) {
                ull p0, p1, q0, q1, s;
                asm("ld.shared.v2.u64 {%0,%1},[%2];" : "=l"(p0), "=l"(p1) : "r"(sb + k2 * 32));
                asm("ld.shared.v2.u64 {%0,%1},[%2];" : "=l"(q0), "=l"(q1) : "r"(sb + k2 * 32 + 16));
                asm("fma.rn.f32x2 %0,%1,%2,%3;" : "=l"(s) : "l"(ax2), "l"(p0), "l"(q1));
                asm("fma.rn.f32x2 %0,%1,%2,%0;" : "+l"(s) : "l"(ay2), "l"(p1));
                asm("fma.rn.f32x2 %0,%1,%2,%0;" : "+l"(s) : "l"(az2), "l"(q0));
                float s0, s1;
                asm("mov.b64 {%0,%1}, %2;" : "=f"(s0), "=f"(s1) : "l"(s));
                acc0 += ex2f(s0);
                acc1 += ex2f(s1);
            }
        } else {
            // Diagonal tile (j0 == i0): scalar predicated loop; keep j > i, i.e. k > tid.
            const float* f = (const float*)sB;
#pragma unroll 4
            for (int k = 0; k < JT; k++) {
                int k2 = k >> 1, l = k & 1;
                float bx = f[8 * k2 + l];
                float by = f[8 * k2 + 2 + l];
                float bz = f[8 * k2 + 4 + l];
                float bw = f[8 * k2 + 6 + l];
                float s = fmaf(ax, bx, bw);
                s = fmaf(ay, by, s);
                s = fmaf(az, bz, s);
                float e = ex2f(s);
                if (k > tid) acc0 += e;
            }
        }

        // Per-thread factor 2^{aw}, then block reduce -> one partial per block.
        float acc = (acc0 + acc1) * ex2f(aw);
#pragma unroll
        for (int o = 16; o > 0; o >>= 1) acc += __shfl_xor_sync(0xffffffffu, acc, o);
        __shared__ float ws[THREADS / 32];
        const int lane = tid & 31;
        const int wid = tid >> 5;
        if (lane == 0) ws[wid] = acc;
        __syncthreads();
        if (tid == 0) {
            float s = 0.f;
#pragma unroll
            for (int w = 0; w < THREADS / 32; w++) s += ws[w];
            g_part[b] = s;
        }
    } else {
        if (tid == 0) g_part[b] = 0.f;
    }

    // ---- Last-block final reduction (threadfence reduction pattern) ----
    __shared__ unsigned s_last;
    if (tid == 0) {
        __threadfence();
        unsigned t = atomicAdd(&g_ticket, 1u);
        s_last = (t == gridDim.x - 1) ? 1u : 0u;
    }
    __syncthreads();
    if (!s_last) return;

    // This block observes all g_part writes (acquire via the atomic + fence chain;
    // L1 has not cached g_part in this launch, and we force L2 reads with ldcg).
    double s0 = 0.0, s1 = 0.0, s2 = 0.0;   // xz, xx(upper), zz(upper)
    for (int k = tid; k < tpj; k += THREADS) {
        s0 += (double)__ldcg(&g_part[k]);
        s1 += (double)__ldcg(&g_part[tpj + k]);
        s2 += (double)__ldcg(&g_part[2 * tpj + k]);
    }
#pragma unroll
    for (int o = 16; o > 0; o >>= 1) {
        s0 += __shfl_xor_sync(0xffffffffu, s0, o);
        s1 += __shfl_xor_sync(0xffffffffu, s1, o);
        s2 += __shfl_xor_sync(0xffffffffu, s2, o);
    }
    __shared__ double r0[THREADS / 32], r1[THREADS / 32], r2[THREADS / 32];
    const int lane = tid & 31, wid = tid >> 5;
    if (lane == 0) { r0[wid] = s0; r1[wid] = s1; r2[wid] = s2; }
    __syncthreads();
    if (tid == 0) {
        double t0 = 0, t1 = 0, t2 = 0;
#pragma unroll
        for (int w = 0; w < THREADS / 32; w++) { t0 += r0[w]; t1 += r1[w]; t2 += r2[w]; }
        double inv = 1.0 / sqrt(2.0 * 3.14159265358979323846 * (double)ks[0]);
        double nn = (double)n * (double)n;
        double mxz = t0 * inv / nn;
        double mxx = (2.0 * t1 + (double)n) * inv / nn;   // upper*2 + diagonal (exp(0)=1)
        double mzz = (2.0 * t2 + (double)n) * inv / nn;
        double r = log(sqrt(mxx * mzz + 1e-5) / (mxz + 1e-5));
        out[6 * n] = (float)(r * (double)theta[0]);
        g_ticket = 0;   // reset for next graph replay (ordered before kernel end)
    }
}

extern "C" void kernel_launch(void* const* d_in, const int* in_sizes, int n_in,
                              void* d_out, int out_size) {
    const float* x     = (const float*)d_in[0];
    const float* z     = (const float*)d_in[1];
    const float* ks    = (const float*)d_in[2];
    const float* theta = (const float*)d_in[3];
    float* out = (float*)d_out;

    const int n = in_sizes[0] / 3;          // 8192
    const int iTiles = n / THREADS;
    const int jSlabs = n / JT;
    const int tpj = iTiles * jSlabs;

    pair_kernel<<<3 * tpj, THREADS>>>(x, z, ks, theta, out, n);
}

// round 5
// speedup vs baseline: 1.2856x; 1.2856x over previous
#include <cuda_runtime.h>
#include <math.h>

#define THREADS 256
#define JT      256

typedef unsigned long long ull;

// 12 fp64 accumulator slots: job*4 + (rem&3). Zero-initialized at module load;
// final_kernel resets them after reading so every graph replay starts from 0.
__device__ double g_acc[12];

__device__ __forceinline__ float ex2f(float v) {
    float y;
    asm("ex2.approx.ftz.f32 %0, %1;" : "=f"(y) : "f"(v));
    return y;
}

// Fused kernel: inline prep (scale + pack), passthrough copy, pair sums.
// Job 0: xz (full grid), job 1: xx (strict upper), job 2: zz (strict upper).
// With JT == THREADS, symmetric blocks: js < it -> empty, js == it -> boundary,
// js > it -> full (predicate-free packed f32x2 loop).
__global__ void __launch_bounds__(THREADS) pair_kernel(
    const float* __restrict__ x, const float* __restrict__ z,
    const float* __restrict__ ks, float* __restrict__ out, int n)
{
    const int iTiles = n / THREADS;
    const int jSlabs = n / JT;
    const int tpj = iTiles * jSlabs;

    const int b = blockIdx.x;
    const int job = b / tpj;
    const int rem = b - job * tpj;
    const int it = rem % iTiles;
    const int js = rem / iTiles;
    const int tid = threadIdx.x;

    // ---- Passthrough copy: out[0..3n) = x, out[3n..6n) = z, sliced by block ----
    {
        const int total = 6 * n;
        const int per = (total + gridDim.x - 1) / gridDim.x;
        const int start = b * per;
        const int stop = min(start + per, total);
        for (int idx = start + tid; idx < stop; idx += THREADS)
            out[idx] = (idx < 3 * n) ? x[idx] : z[idx - 3 * n];
    }

    const bool sym = (job >= 1);
    if (sym && js < it) return;          // entirely below diagonal: no pairs

    const int i0 = it * THREADS;
    const int j0 = js * JT;

    const float* A = (job == 2) ? z : x;
    const float* B = (job == 1) ? x : z;

    const float sc = sqrtf(1.4426950408889634f / ks[0]);   // sqrt(log2e / ks)

    // B slab, packed-pairs layout for f32x2 math:
    //   sB[2*g]   = (bx0, bx1, by0, by1)
    //   sB[2*g+1] = (bz0, bz1, w0,  w1)    w = -|b|^2 (scaled)
    __shared__ float4 sB[JT];
    for (int g = tid; g < JT / 2; g += THREADS) {
        int ja = j0 + 2 * g, jb = ja + 1;
        float b0x = B[3 * ja]     * sc, b0y = B[3 * ja + 1] * sc, b0z = B[3 * ja + 2] * sc;
        float b1x = B[3 * jb]     * sc, b1y = B[3 * jb + 1] * sc, b1z = B[3 * jb + 2] * sc;
        float w0 = -(b0x * b0x + b0y * b0y + b0z * b0z);
        float w1 = -(b1x * b1x + b1y * b1y + b1z * b1z);
        sB[2 * g]     = make_float4(b0x, b1x, b0y, b1y);
        sB[2 * g + 1] = make_float4(b0z, b1z, w0, w1);
    }

    // A point for this thread: doubled scaled coords; aw = -|a|^2.
    const int i = i0 + tid;
    const float ax = A[3 * i]     * sc * 2.f;
    const float ay = A[3 * i + 1] * sc * 2.f;
    const float az = A[3 * i + 2] * sc * 2.f;
    const float aw = -0.25f * (ax * ax + ay * ay + az * az);
    __syncthreads();

    float acc0 = 0.f, acc1 = 0.f;

    if (!(sym && js == it)) {
        // Full tile: predicate-free packed loop, 2 j's per iteration.
        ull ax2, ay2, az2;
        asm("mov.b64 %0, {%1,%1};" : "=l"(ax2) : "f"(ax));
        asm("mov.b64 %0, {%1,%1};" : "=l"(ay2) : "f"(ay));
        asm("mov.b64 %0, {%1,%1};" : "=l"(az2) : "f"(az));
        unsigned sb = (unsigned)__cvta_generic_to_shared(sB);
#pragma unroll 8
        for (int k2 = 0; k2 < JT / 2; k2++) {
            ull p0, p1, q0, q1, s;
            asm("ld.shared.v2.u64 {%0,%1},[%2];" : "=l"(p0), "=l"(p1) : "r"(sb + k2 * 32));
            asm("ld.shared.v2.u64 {%0,%1},[%2];" : "=l"(q0), "=l"(q1) : "r"(sb + k2 * 32 + 16));
            asm("fma.rn.f32x2 %0,%1,%2,%3;" : "=l"(s) : "l"(ax2), "l"(p0), "l"(q1));
            asm("fma.rn.f32x2 %0,%1,%2,%0;" : "+l"(s) : "l"(ay2), "l"(p1));
            asm("fma.rn.f32x2 %0,%1,%2,%0;" : "+l"(s) : "l"(az2), "l"(q0));
            float s0, s1;
            asm("mov.b64 {%0,%1}, %2;" : "=f"(s0), "=f"(s1) : "l"(s));
            acc0 += ex2f(s0);
            acc1 += ex2f(s1);
        }
    } else {
        // Diagonal tile (j0 == i0): scalar predicated loop; keep j > i, i.e. k > tid.
        const float* f = (const float*)sB;
#pragma unroll 4
        for (int k = 0; k < JT; k++) {
            int k2 = k >> 1, l = k & 1;
            float bx = f[8 * k2 + l];
            float by = f[8 * k2 + 2 + l];
            float bz = f[8 * k2 + 4 + l];
            float bw = f[8 * k2 + 6 + l];
            float s = fmaf(ax, bx, bw);
            s = fmaf(ay, by, s);
            s = fmaf(az, bz, s);
            float e = ex2f(s);
            if (k > tid) acc0 += e;
        }
    }

    // Per-thread factor 2^{aw}, then block reduce -> one fp64 RED per block.
    float acc = (acc0 + acc1) * ex2f(aw);
#pragma unroll
    for (int o = 16; o > 0; o >>= 1) acc += __shfl_xor_sync(0xffffffffu, acc, o);
    __shared__ float ws[THREADS / 32];
    const int lane = tid & 31;
    const int wid = tid >> 5;
    if (lane == 0) ws[wid] = acc;
    __syncthreads();
    if (tid == 0) {
        float s = 0.f;
#pragma unroll
        for (int w = 0; w < THREADS / 32; w++) s += ws[w];
        atomicAdd(&g_acc[job * 4 + (rem & 3)], (double)s);
    }
}

__global__ void final_kernel(const float* __restrict__ ks,
                             const float* __restrict__ theta,
                             float* __restrict__ out_scalar, int n) {
    double t0 = 0.0, t1 = 0.0, t2 = 0.0;   // xz, xx(upper), zz(upper)
#pragma unroll
    for (int k = 0; k < 4; k++) {
        t0 += g_acc[k];
        t1 += g_acc[4 + k];
        t2 += g_acc[8 + k];
    }
    double inv = 1.0 / sqrt(2.0 * 3.14159265358979323846 * (double)ks[0]);
    double nn = (double)n * (double)n;
    double mxz = t0 * inv / nn;
    double mxx = (2.0 * t1 + (double)n) * inv / nn;   // upper*2 + diagonal (exp(0)=1)
    double mzz = (2.0 * t2 + (double)n) * inv / nn;
    double r = log(sqrt(mxx * mzz + 1e-5) / (mxz + 1e-5));
    *out_scalar = (float)(r * (double)theta[0]);
    // Reset accumulators for the next graph replay.
#pragma unroll
    for (int k = 0; k < 12; k++) g_acc[k] = 0.0;
}

extern "C" void kernel_launch(void* const* d_in, const int* in_sizes, int n_in,
                              void* d_out, int out_size) {
    const float* x     = (const float*)d_in[0];
    const float* z     = (const float*)d_in[1];
    const float* ks    = (const float*)d_in[2];
    const float* theta = (const float*)d_in[3];
    float* out = (float*)d_out;

    const int n = in_sizes[0] / 3;          // 8192
    const int iTiles = n / THREADS;
    const int jSlabs = n / JT;
    const int tpj = iTiles * jSlabs;

    pair_kernel<<<3 * tpj, THREADS>>>(x, z, ks, out, n);
    final_kernel<<<1, 1>>>(ks, theta, out + 6 * n, n);
}

// round 7
// speedup vs baseline: 1.9297x; 1.5011x over previous
#include <cuda_runtime.h>
#include <math.h>

#define THREADS 256
#define JT      256

typedef unsigned long long ull;

// 12 fp64 accumulator slots: job*4 + (rem&3). Zero-initialized at module load;
// the last block resets them after reading so every graph replay starts from 0.
__device__ double   g_acc[12];
__device__ unsigned g_ticket = 0;

__device__ __forceinline__ float ex2f(float v) {
    float y;
    asm("ex2.approx.ftz.f32 %0, %1;" : "=f"(y) : "f"(v));
    return y;
}

__device__ __forceinline__ void red_relaxed_f64(double* p, double v) {
    asm volatile("red.relaxed.gpu.global.add.f64 [%0], %1;" :: "l"(p), "d"(v) : "memory");
}
__device__ __forceinline__ unsigned atom_acqrel_inc(unsigned* p) {
    unsigned old;
    asm volatile("atom.acq_rel.gpu.global.add.u32 %0, [%1], 1;"
                 : "=r"(old) : "l"(p) : "memory");
    return old;
}
__device__ __forceinline__ double ld_acquire_f64(const double* p) {
    double v;
    asm volatile("ld.acquire.gpu.global.f64 %0, [%1];" : "=d"(v) : "l"(p) : "memory");
    return v;
}

// Single fused kernel: inline prep (scale + pack), passthrough copy, pair sums,
// fence-free last-block epilogue via acq_rel ticket atomic.
// Job 0: xz (full grid), job 1: xx (strict upper), job 2: zz (strict upper).
__global__ void __launch_bounds__(THREADS) pair_kernel(
    const float* __restrict__ x, const float* __restrict__ z,
    const float* __restrict__ ks, const float* __restrict__ theta,
    float* __restrict__ out, int n)
{
    const int iTiles = n / THREADS;
    const int jSlabs = n / JT;
    const int tpj = iTiles * jSlabs;

    const int b = blockIdx.x;
    const int job = b / tpj;
    const int rem = b - job * tpj;
    const int it = rem % iTiles;
    const int js = rem / iTiles;
    const int tid = threadIdx.x;

    // ---- Passthrough copy: out[0..3n) = x, out[3n..6n) = z, sliced by block ----
    {
        const int total = 6 * n;
        const int per = (total + gridDim.x - 1) / gridDim.x;
        const int start = b * per;
        const int stop = min(start + per, total);
        for (int idx = start + tid; idx < stop; idx += THREADS)
            out[idx] = (idx < 3 * n) ? x[idx] : z[idx - 3 * n];
    }

    const bool sym = (job >= 1);
    const bool empty = sym && (js < it);     // entirely below diagonal: no pairs

    if (!empty) {
        const int i0 = it * THREADS;
        const int j0 = js * JT;

        const float* A = (job == 2) ? z : x;
        const float* B = (job == 1) ? x : z;

        const float sc = sqrtf(1.4426950408889634f / ks[0]);   // sqrt(log2e / ks)

        // B slab, packed-pairs layout for f32x2 math:
        //   sB[2*g]   = (bx0, bx1, by0, by1)
        //   sB[2*g+1] = (bz0, bz1, w0,  w1)    w = -|b|^2 (scaled)
        __shared__ float4 sB[JT];
        for (int g = tid; g < JT / 2; g += THREADS) {
            int ja = j0 + 2 * g, jb = ja + 1;
            float b0x = B[3 * ja]     * sc, b0y = B[3 * ja + 1] * sc, b0z = B[3 * ja + 2] * sc;
            float b1x = B[3 * jb]     * sc, b1y = B[3 * jb + 1] * sc, b1z = B[3 * jb + 2] * sc;
            float w0 = -(b0x * b0x + b0y * b0y + b0z * b0z);
            float w1 = -(b1x * b1x + b1y * b1y + b1z * b1z);
            sB[2 * g]     = make_float4(b0x, b1x, b0y, b1y);
            sB[2 * g + 1] = make_float4(b0z, b1z, w0, w1);
        }

        // A point for this thread: doubled scaled coords; aw = -|a|^2.
        const int i = i0 + tid;
        const float ax = A[3 * i]     * sc * 2.f;
        const float ay = A[3 * i + 1] * sc * 2.f;
        const float az = A[3 * i + 2] * sc * 2.f;
        const float aw = -0.25f * (ax * ax + ay * ay + az * az);
        __syncthreads();

        float acc0 = 0.f, acc1 = 0.f;

        if (!(sym && js == it)) {
            // Full tile: predicate-free packed loop, 2 j's per iteration.
            ull ax2, ay2, az2;
            asm("mov.b64 %0, {%1,%1};" : "=l"(ax2) : "f"(ax));
            asm("mov.b64 %0, {%1,%1};" : "=l"(ay2) : "f"(ay));
            asm("mov.b64 %0, {%1,%1};" : "=l"(az2) : "f"(az));
            unsigned sb = (unsigned)__cvta_generic_to_shared(sB);
#pragma unroll 8
            for (int k2 = 0; k2 < JT / 2; k2++) {
                ull p0, p1, q0, q1, s;
                asm("ld.shared.v2.u64 {%0,%1},[%2];" : "=l"(p0), "=l"(p1) : "r"(sb + k2 * 32));
                asm("ld.shared.v2.u64 {%0,%1},[%2];" : "=l"(q0), "=l"(q1) : "r"(sb + k2 * 32 + 16));
                asm("fma.rn.f32x2 %0,%1,%2,%3;" : "=l"(s) : "l"(ax2), "l"(p0), "l"(q1));
                asm("fma.rn.f32x2 %0,%1,%2,%0;" : "+l"(s) : "l"(ay2), "l"(p1));
                asm("fma.rn.f32x2 %0,%1,%2,%0;" : "+l"(s) : "l"(az2), "l"(q0));
                float s0, s1;
                asm("mov.b64 {%0,%1}, %2;" : "=f"(s0), "=f"(s1) : "l"(s));
                acc0 += ex2f(s0);
                acc1 += ex2f(s1);
            }
        } else {
            // Diagonal tile (j0 == i0): scalar predicated loop; keep j > i, i.e. k > tid.
            const float* f = (const float*)sB;
#pragma unroll 4
            for (int k = 0; k < JT; k++) {
                int k2 = k >> 1, l = k & 1;
                float bx = f[8 * k2 + l];
                float by = f[8 * k2 + 2 + l];
                float bz = f[8 * k2 + 4 + l];
                float bw = f[8 * k2 + 6 + l];
                float s = fmaf(ax, bx, bw);
                s = fmaf(ay, by, s);
                s = fmaf(az, bz, s);
                float e = ex2f(s);
                if (k > tid) acc0 += e;
            }
        }

        // Per-thread factor 2^{aw}, then block reduce -> one fp64 RED per block.
        float acc = (acc0 + acc1) * ex2f(aw);
#pragma unroll
        for (int o = 16; o > 0; o >>= 1) acc += __shfl_xor_sync(0xffffffffu, acc, o);
        __shared__ float ws[THREADS / 32];
        const int lane = tid & 31;
        const int wid = tid >> 5;
        if (lane == 0) ws[wid] = acc;
        __syncthreads();
        if (tid == 0) {
            float s = 0.f;
#pragma unroll
            for (int w = 0; w < THREADS / 32; w++) s += ws[w];
            red_relaxed_f64(&g_acc[job * 4 + (rem & 3)], (double)s);
        }
    }

    // ---- Fence-free last-block epilogue (tid 0 only) ----
    if (tid != 0) return;
    unsigned t = atom_acqrel_inc(&g_ticket);   // release: orders the RED above
    if (t != gridDim.x - 1) return;

    // Last block: all REDs are visible (acquire side of the acq_rel ticket).
    double t0 = 0.0, t1 = 0.0, t2 = 0.0;       // xz, xx(upper), zz(upper)
#pragma unroll
    for (int k = 0; k < 4; k++) {
        t0 += ld_acquire_f64(&g_acc[k]);
        t1 += ld_acquire_f64(&g_acc[4 + k]);
        t2 += ld_acquire_f64(&g_acc[8 + k]);
    }
    double inv = 1.0 / sqrt(2.0 * 3.14159265358979323846 * (double)ks[0]);
    double nn = (double)n * (double)n;
    double mxz = t0 * inv / nn;
    double mxx = (2.0 * t1 + (double)n) * inv / nn;   // upper*2 + diagonal (exp(0)=1)
    double mzz = (2.0 * t2 + (double)n) * inv / nn;
    double r = log(sqrt(mxx * mzz + 1e-5) / (mxz + 1e-5));
    out[6 * n] = (float)(r * (double)theta[0]);

    // Reset for the next graph replay (ordered before kernel completion).
#pragma unroll
    for (int k = 0; k < 12; k++) g_acc[k] = 0.0;
    g_ticket = 0;
}

extern "C" void kernel_launch(void* const* d_in, const int* in_sizes, int n_in,
                              void* d_out, int out_size) {
    const float* x     = (const float*)d_in[0];
    const float* z     = (const float*)d_in[1];
    const float* ks    = (const float*)d_in[2];
    const float* theta = (const float*)d_in[3];
    float* out = (float*)d_out;

    const int n = in_sizes[0] / 3;          // 8192
    const int iTiles = n / THREADS;
    const int jSlabs = n / JT;
    const int tpj = iTiles * jSlabs;

    pair_kernel<<<3 * tpj, THREADS>>>(x, z, ks, theta, out, n);
}